// round 1
// baseline (speedup 1.0000x reference)
#include <cuda_runtime.h>

#define BATCH 4
#define C 64
#define N 8192
#define O 128
#define KNN 20
#define C2 128
#define MT 128
#define XS_STRIDE 68
#define NB 32
#define FT_STRIDE 24

// Scratch (allocation-free rule: __device__ globals)
__device__ float g_xt[BATCH * N * C];    // (b, n, c) transposed points
__device__ float g_xx[BATCH * N];        // squared norms
__device__ int   g_idx[BATCH * N * KNN]; // knn indices

// ---------------------------------------------------------------------------
// Kernel 1: transpose x (b,c,n) -> xt (b,n,c) and compute squared norms
// ---------------------------------------------------------------------------
__global__ __launch_bounds__(256) void prep_kernel(const float* __restrict__ x) {
    int gid = blockIdx.x * 256 + threadIdx.x;     // gid = b*N + n
    int b = gid >> 13;                            // N = 8192 = 2^13
    int n = gid & (N - 1);
    const float* xb = x + (size_t)b * C * N;
    float v[C];
    float s = 0.f;
#pragma unroll
    for (int c = 0; c < C; c++) {
        v[c] = xb[(size_t)c * N + n];             // coalesced across threads
        s = fmaf(v[c], v[c], s);
    }
    g_xx[gid] = s;
    float4* dst = (float4*)(g_xt + (size_t)gid * C);
#pragma unroll
    for (int i = 0; i < C / 4; i++)
        dst[i] = make_float4(v[4*i], v[4*i+1], v[4*i+2], v[4*i+3]);
}

// ---------------------------------------------------------------------------
// Kernel 2: brute-force kNN, one query per thread, streaming top-20 in regs.
// Only the SET of indices matters (softmax over k + sum over k is
// permutation-invariant), so no sorting needed.
// ---------------------------------------------------------------------------
__global__ __launch_bounds__(64) void knn_kernel(const float* __restrict__ x) {
    __shared__ float xs[MT * XS_STRIDE];  // candidate tile, transposed [mm][c]
    __shared__ float xxs[MT];

    int b = blockIdx.y;
    int q = blockIdx.x * 64 + threadIdx.x;
    const float* xb = x + (size_t)b * C * N;

    // Load query vector (coalesced) into registers as float4s
    float4 qv[16];
    float xxq = 0.f;
    {
        float tmp[C];
#pragma unroll
        for (int c = 0; c < C; c++) tmp[c] = xb[(size_t)c * N + q];
#pragma unroll
        for (int i = 0; i < 16; i++) {
            qv[i] = make_float4(tmp[4*i], tmp[4*i+1], tmp[4*i+2], tmp[4*i+3]);
            xxq += tmp[4*i]*tmp[4*i] + tmp[4*i+1]*tmp[4*i+1]
                 + tmp[4*i+2]*tmp[4*i+2] + tmp[4*i+3]*tmp[4*i+3];
        }
    }

    float bd[KNN];
    int   bi[KNN];
#pragma unroll
    for (int i = 0; i < KNN; i++) { bd[i] = 3.4e38f; bi[i] = 0; }
    float worst = 3.4e38f;
    int   wpos  = 0;

    for (int m0 = 0; m0 < N; m0 += MT) {
        __syncthreads();
        // Cooperative tile load: x[b][c][m0..m0+MT) -> xs[mm][c] (transposed)
        for (int i = threadIdx.x; i < C * MT; i += 64) {
            int c  = i >> 7;          // i / MT
            int mm = i & (MT - 1);
            xs[mm * XS_STRIDE + c] = xb[(size_t)c * N + m0 + mm];
        }
        for (int i = threadIdx.x; i < MT; i += 64)
            xxs[i] = g_xx[b * N + m0 + i];
        __syncthreads();

        for (int mm = 0; mm < MT; mm++) {
            const float4* xr = (const float4*)(xs + mm * XS_STRIDE);
            float d0 = 0.f, d1 = 0.f, d2 = 0.f, d3 = 0.f;
#pragma unroll
            for (int i = 0; i < 16; i++) {
                float4 xv = xr[i];                 // broadcast LDS.128
                d0 = fmaf(qv[i].x, xv.x, d0);
                d1 = fmaf(qv[i].y, xv.y, d1);
                d2 = fmaf(qv[i].z, xv.z, d2);
                d3 = fmaf(qv[i].w, xv.w, d3);
            }
            float dot = (d0 + d1) + (d2 + d3);
            float d = fmaf(-2.f, dot, xxq + xxs[mm]);
            if (d < worst) {
                int m = m0 + mm;
                // replace current worst slot (unrolled predicated — keeps regs)
#pragma unroll
                for (int i = 0; i < KNN; i++)
                    if (i == wpos) { bd[i] = d; bi[i] = m; }
                worst = bd[0]; wpos = 0;
#pragma unroll
                for (int i = 1; i < KNN; i++)
                    if (bd[i] > worst) { worst = bd[i]; wpos = i; }
            }
        }
    }

    int* op = g_idx + (size_t)(b * N + q) * KNN;
#pragma unroll
    for (int i = 0; i < KNN; i++) op[i] = bi[i];
}

// ---------------------------------------------------------------------------
// Kernel 3: gather feats, h = feats@W1^T, softmax over k, g[c]=sum_k f*gate,
// out[o] = sum_c g[c]*W2[o][c].   256 threads = 2 sub-groups of 128, each
// processing its own point; W1/W2 staged transposed in smem once per block.
// ---------------------------------------------------------------------------
__global__ __launch_bounds__(256, 1) void mlp_kernel(
    const float* __restrict__ W1, const float* __restrict__ W2,
    float* __restrict__ out) {
    extern __shared__ float sm[];
    float* W1t = sm;                          // [c*129 + d] = W1[d][c]
    float* W2t = W1t + 128 * 129;             // [c*129 + o] = W2[o][c]
    float* fT  = W2t + 128 * 129;             // 2 x [c*24 + k]
    float* cs  = fT + 2 * 128 * FT_STRIDE;    // 2 x 64 (center)
    float* gs  = cs + 2 * 64;                 // 2 x 128
    int*   nbs = (int*)(gs + 2 * 128);        // 2 x 32

    int tid = threadIdx.x;
    int sub = tid >> 7;
    int t   = tid & 127;
    int b   = blockIdx.y;
    int n0  = blockIdx.x * NB;

    // Stage W1, W2 transposed (conflict-free writes: stride 129)
    for (int i = tid; i < 128 * 128; i += 256) {
        int d = i >> 7, c = i & 127;
        W1t[c * 129 + d] = W1[i];
        W2t[c * 129 + d] = W2[i];
    }

    float* fTs  = fT  + sub * 128 * FT_STRIDE;
    float* css  = cs  + sub * 64;
    float* gss  = gs  + sub * 128;
    int*   nbss = nbs + sub * 32;

    for (int it = 0; it < NB / 2; it++) {
        int n = n0 + 2 * it + sub;
        size_t base = (size_t)b * N + n;

        // phase 0: indices + center
        if (t < KNN) nbss[t] = g_idx[base * KNN + t];
        if (t < C)   css[t]  = g_xt[base * C + t];
        __syncthreads();

        // phase 1: featsT[c][k] : first 64 c = nbr - center, next 64 = center
        for (int j = t; j < KNN * C; j += 128) {
            int k = j >> 6;
            int c = j & 63;
            float cv = css[c];
            float v  = g_xt[((size_t)b * N + nbss[k]) * C + c];
            fTs[c * FT_STRIDE + k]        = v - cv;
            fTs[(64 + c) * FT_STRIDE + k] = cv;
        }
        __syncthreads();

        // phase 2: h[k] for this thread's d=t column, softmax over k, g[t]
        float acc[KNN];
#pragma unroll
        for (int k = 0; k < KNN; k++) acc[k] = 0.f;
#pragma unroll 4
        for (int c = 0; c < C2; c++) {
            float w = W1t[c * 129 + t];
            const float4* fr = (const float4*)(fTs + c * FT_STRIDE);
#pragma unroll
            for (int k4 = 0; k4 < 5; k4++) {
                float4 f = fr[k4];                 // broadcast LDS.128
                acc[4*k4+0] = fmaf(f.x, w, acc[4*k4+0]);
                acc[4*k4+1] = fmaf(f.y, w, acc[4*k4+1]);
                acc[4*k4+2] = fmaf(f.z, w, acc[4*k4+2]);
                acc[4*k4+3] = fmaf(f.w, w, acc[4*k4+3]);
            }
        }
        float mx = acc[0];
#pragma unroll
        for (int k = 1; k < KNN; k++) mx = fmaxf(mx, acc[k]);
        float ssum = 0.f;
#pragma unroll
        for (int k = 0; k < KNN; k++) { acc[k] = __expf(acc[k] - mx); ssum += acc[k]; }
        float inv = 1.f / ssum;

        float gacc = 0.f;
        {
            const float4* fr = (const float4*)(fTs + t * FT_STRIDE);
#pragma unroll
            for (int k4 = 0; k4 < 5; k4++) {
                float4 f = fr[k4];
                gacc = fmaf(f.x, acc[4*k4+0], gacc);
                gacc = fmaf(f.y, acc[4*k4+1], gacc);
                gacc = fmaf(f.z, acc[4*k4+2], gacc);
                gacc = fmaf(f.w, acc[4*k4+3], gacc);
            }
        }
        gss[t] = gacc * inv;
        __syncthreads();

        // phase 3: out[b][o=t][n] = sum_c g[c] * W2[o][c]
        float oacc = 0.f;
#pragma unroll 8
        for (int c = 0; c < C2; c++)
            oacc = fmaf(gss[c], W2t[c * 129 + t], oacc);
        out[((size_t)b * O + t) * N + n] = oacc;
        __syncthreads();
    }
}

static const int MLP_SMEM_BYTES =
    (128 * 129 * 2 + 2 * 128 * FT_STRIDE + 2 * 64 + 2 * 128) * 4 + 2 * 32 * 4;

extern "C" void kernel_launch(void* const* d_in, const int* in_sizes, int n_in,
                              void* d_out, int out_size) {
    (void)in_sizes; (void)n_in; (void)out_size;
    const float* x  = (const float*)d_in[0];
    const float* W1 = (const float*)d_in[1];
    const float* W2 = (const float*)d_in[2];
    float* out = (float*)d_out;

    prep_kernel<<<(BATCH * N) / 256, 256>>>(x);
    knn_kernel<<<dim3(N / 64, BATCH), 64>>>(x);
    cudaFuncSetAttribute(mlp_kernel, cudaFuncAttributeMaxDynamicSharedMemorySize,
                         MLP_SMEM_BYTES);
    mlp_kernel<<<dim3(N / NB, BATCH), 256, MLP_SMEM_BYTES>>>(W1, W2, out);
}

// round 2
// speedup vs baseline: 1.0402x; 1.0402x over previous
#include <cuda_runtime.h>

#define BATCH 4
#define C 64
#define N 8192
#define O 128
#define KNN 20
#define C2 128
#define MT 128
#define XS_STRIDE 68       // floats; 17 float4
#define NB 32
#define FT_STRIDE 24

// Scratch (allocation-free rule: __device__ globals)
__device__ float g_xt[BATCH * N * C];    // (b, n, c) transposed points
__device__ float g_xx[BATCH * N];        // squared norms
__device__ int   g_idx[BATCH * N * KNN]; // knn indices
__device__ float g_W1T[C2 * C2];         // [c][d] = W1[d][c]
__device__ float g_W2T[C2 * C2];         // [c][o] = W2[o][c]

// ---------------------------------------------------------------------------
// Kernel 1: transpose x (b,c,n) -> xt (b,n,c) and compute squared norms
// ---------------------------------------------------------------------------
__global__ __launch_bounds__(256) void prep_kernel(const float* __restrict__ x) {
    int gid = blockIdx.x * 256 + threadIdx.x;     // gid = b*N + n
    int b = gid >> 13;
    int n = gid & (N - 1);
    const float* xb = x + (size_t)b * C * N;
    float v[C];
    float s = 0.f;
#pragma unroll
    for (int c = 0; c < C; c++) {
        v[c] = xb[(size_t)c * N + n];             // coalesced across threads
        s = fmaf(v[c], v[c], s);
    }
    g_xx[gid] = s;
    float4* dst = (float4*)(g_xt + (size_t)gid * C);
#pragma unroll
    for (int i = 0; i < C / 4; i++)
        dst[i] = make_float4(v[4*i], v[4*i+1], v[4*i+2], v[4*i+3]);
}

// ---------------------------------------------------------------------------
// Kernel 1b: transpose W1, W2 into global scratch (tiny)
// ---------------------------------------------------------------------------
__global__ __launch_bounds__(256) void wtrans_kernel(const float* __restrict__ W1,
                                                     const float* __restrict__ W2) {
    int i = blockIdx.x * 256 + threadIdx.x;       // i = d*128 + c
    int d = i >> 7, c = i & 127;
    g_W1T[c * C2 + d] = W1[i];
    g_W2T[c * C2 + d] = W2[i];
}

// ---------------------------------------------------------------------------
// streaming top-KNN insertion (register arrays, fully unrolled predication)
// ---------------------------------------------------------------------------
__device__ __forceinline__ void topk_insert(float d, int m, float* bd, int* bi,
                                            float& worst, int& wpos) {
    if (d < worst) {
#pragma unroll
        for (int i = 0; i < KNN; i++)
            if (i == wpos) { bd[i] = d; bi[i] = m; }
        worst = bd[0]; wpos = 0;
#pragma unroll
        for (int i = 1; i < KNN; i++)
            if (bd[i] > worst) { worst = bd[i]; wpos = i; }
    }
}

// ---------------------------------------------------------------------------
// Kernel 2: brute-force kNN. 128 threads/block; 64 queries/block; each query
// handled by TWO threads scanning disjoint halves of every 128-candidate
// shared tile (doubles warps/SM: 6.9 -> 13.8). Lists merged at the end.
// Only the SET of the 20 nearest matters (softmax over k is permutation-
// invariant), so no sorting needed anywhere.
// ---------------------------------------------------------------------------
__global__ __launch_bounds__(128) void knn_kernel() {
    __shared__ float xs[MT * XS_STRIDE];   // candidate tile [mm][c], 34.8KB
    __shared__ float xxs[MT];

    int t    = threadIdx.x;
    int half = t >> 6;                     // candidate half within each tile
    int ql   = t & 63;
    int b    = blockIdx.y;
    int q    = blockIdx.x * 64 + ql;
    size_t bN = (size_t)b * N;

    // Query vector (contiguous row of g_xt)
    float4 qv[16];
    {
        const float4* qp = (const float4*)(g_xt + (bN + q) * C);
#pragma unroll
        for (int i = 0; i < 16; i++) qv[i] = qp[i];
    }
    float xxq = g_xx[bN + q];

    float bd[KNN];
    int   bi[KNN];
#pragma unroll
    for (int i = 0; i < KNN; i++) { bd[i] = 3.4e38f; bi[i] = 0; }
    float worst = 3.4e38f;
    int   wpos  = 0;

    for (int m0 = 0; m0 < N; m0 += MT) {
        __syncthreads();
        // Linear, fully-coalesced tile load from g_xt
        {
            const float4* src = (const float4*)(g_xt + (bN + m0) * C);
            float4* dst = (float4*)xs;
#pragma unroll
            for (int i = 0; i < (MT * C / 4) / 128; i++) {
                int j = i * 128 + t;
                int row = j >> 4, c4 = j & 15;
                dst[row * 17 + c4] = src[j];
            }
            xxs[t] = g_xx[bN + m0 + t];
        }
        __syncthreads();

        int mmb = half * 64;
#pragma unroll 1
        for (int mm = 0; mm < 64; mm += 2) {
            const float4* xr0 = (const float4*)(xs + (mmb + mm) * XS_STRIDE);
            const float4* xr1 = xr0 + 17;
            float a0 = 0.f, a1 = 0.f, a2 = 0.f, a3 = 0.f;
            float c0 = 0.f, c1 = 0.f, c2 = 0.f, c3 = 0.f;
#pragma unroll
            for (int i = 0; i < 16; i++) {
                float4 x0 = xr0[i];
                float4 x1 = xr1[i];
                a0 = fmaf(qv[i].x, x0.x, a0);
                a1 = fmaf(qv[i].y, x0.y, a1);
                a2 = fmaf(qv[i].z, x0.z, a2);
                a3 = fmaf(qv[i].w, x0.w, a3);
                c0 = fmaf(qv[i].x, x1.x, c0);
                c1 = fmaf(qv[i].y, x1.y, c1);
                c2 = fmaf(qv[i].z, x1.z, c2);
                c3 = fmaf(qv[i].w, x1.w, c3);
            }
            float dot0 = (a0 + a1) + (a2 + a3);
            float dot1 = (c0 + c1) + (c2 + c3);
            float d0 = fmaf(-2.f, dot0, xxq + xxs[mmb + mm]);
            float d1 = fmaf(-2.f, dot1, xxq + xxs[mmb + mm + 1]);
            topk_insert(d0, m0 + mmb + mm,     bd, bi, worst, wpos);
            topk_insert(d1, m0 + mmb + mm + 1, bd, bi, worst, wpos);
        }
    }

    // Merge the two half-lists per query (reuse xs as scratch)
    __syncthreads();
    float* md = xs;                         // [128][KNN] dists
    int*   mi = (int*)(xs + 128 * KNN);     // [128][KNN] idxs
#pragma unroll
    for (int i = 0; i < KNN; i++) { md[t * KNN + i] = bd[i]; mi[t * KNN + i] = bi[i]; }
    __syncthreads();
    if (t < 64) {
#pragma unroll
        for (int i = 0; i < KNN; i++) {
            float d = md[(t + 64) * KNN + i];
            int   m = mi[(t + 64) * KNN + i];
            topk_insert(d, m, bd, bi, worst, wpos);
        }
        int* op = g_idx + (bN + q) * KNN;
#pragma unroll
        for (int i = 0; i < KNN; i++) op[i] = bi[i];
    }
}

// ---------------------------------------------------------------------------
// Kernel 3: gather feats, h = feats@W1^T, softmax over k, g[c]=sum_k f*gate,
// out[o] = sum_c g[c]*W2T[c][o].
// 256 threads = 2 independent subgroups of 128 (per-subgroup named barriers),
// each handling one point at a time. W1T/W2T read coalesced from global
// (L1/L2-resident). Outputs staged in smem, written coalesced per block.
// ---------------------------------------------------------------------------
__global__ __launch_bounds__(256) void mlp_kernel(float* __restrict__ out) {
    __shared__ float fT[2 * C2 * FT_STRIDE];   // featsT [c][k] per subgroup
    __shared__ float cs[2 * C];                // center per subgroup
    __shared__ float gs[2 * C2];               // gated-sum per subgroup
    __shared__ int   nbs[2 * 32];              // neighbor idx per subgroup
    __shared__ float obuf[O * 33];             // [o][n-n0] output tile

    int tid = threadIdx.x;
    int sub = tid >> 7;
    int t   = tid & 127;
    int b   = blockIdx.y;
    int n0  = blockIdx.x * NB;
    int barid = sub + 1;

    float* fTs  = fT  + sub * C2 * FT_STRIDE;
    float* css  = cs  + sub * C;
    float* gss  = gs  + sub * C2;
    int*   nbss = nbs + sub * 32;
    size_t bN = (size_t)b * N;

    for (int it = 0; it < NB / 2; it++) {
        int n = n0 + 2 * it + sub;
        size_t base = bN + n;

        // phase 0: indices + center
        if (t < KNN) nbss[t] = g_idx[base * KNN + t];
        if (t < C)   css[t]  = g_xt[base * C + t];
        asm volatile("bar.sync %0, 128;" :: "r"(barid));

        // phase 1: featsT[c][k]: c<64 -> nbr - center, c>=64 -> center
#pragma unroll
        for (int jj = 0; jj < (KNN * C) / 128; jj++) {
            int j = jj * 128 + t;
            int k = j >> 6;
            int c = j & 63;
            float cv = css[c];
            float v  = g_xt[(bN + nbss[k]) * C + c];
            fTs[c * FT_STRIDE + k]        = v - cv;
            fTs[(64 + c) * FT_STRIDE + k] = cv;
        }
        asm volatile("bar.sync %0, 128;" :: "r"(barid));

        // phase 2: h[k] for d=t, softmax over k, then g[t]
        float acc[KNN];
#pragma unroll
        for (int k = 0; k < KNN; k++) acc[k] = 0.f;
#pragma unroll 4
        for (int c = 0; c < C2; c++) {
            float w = g_W1T[c * C2 + t];           // coalesced, L1-cached
            const float4* fr = (const float4*)(fTs + c * FT_STRIDE);
#pragma unroll
            for (int k4 = 0; k4 < 5; k4++) {
                float4 f = fr[k4];                 // broadcast LDS.128
                acc[4*k4+0] = fmaf(f.x, w, acc[4*k4+0]);
                acc[4*k4+1] = fmaf(f.y, w, acc[4*k4+1]);
                acc[4*k4+2] = fmaf(f.z, w, acc[4*k4+2]);
                acc[4*k4+3] = fmaf(f.w, w, acc[4*k4+3]);
            }
        }
        float mx = acc[0];
#pragma unroll
        for (int k = 1; k < KNN; k++) mx = fmaxf(mx, acc[k]);
        float ssum = 0.f;
#pragma unroll
        for (int k = 0; k < KNN; k++) { acc[k] = __expf(acc[k] - mx); ssum += acc[k]; }
        float inv = 1.f / ssum;

        float gacc = 0.f;
        {
            const float4* fr = (const float4*)(fTs + t * FT_STRIDE);
#pragma unroll
            for (int k4 = 0; k4 < 5; k4++) {
                float4 f = fr[k4];
                gacc = fmaf(f.x, acc[4*k4+0], gacc);
                gacc = fmaf(f.y, acc[4*k4+1], gacc);
                gacc = fmaf(f.z, acc[4*k4+2], gacc);
                gacc = fmaf(f.w, acc[4*k4+3], gacc);
            }
        }
        gss[t] = gacc * inv;
        asm volatile("bar.sync %0, 128;" :: "r"(barid));

        // phase 3: obuf[o=t][col] = sum_c g[c] * W2T[c][t]
        float oacc = 0.f;
#pragma unroll 8
        for (int c = 0; c < C2; c++)
            oacc = fmaf(gss[c], g_W2T[c * C2 + t], oacc);   // coalesced LDG
        obuf[t * 33 + 2 * it + sub] = oacc;
        asm volatile("bar.sync %0, 128;" :: "r"(barid));
    }

    // Coalesced output write of the [O x NB] tile
    __syncthreads();
#pragma unroll
    for (int ii = 0; ii < (O * NB) / 256; ii++) {
        int i = ii * 256 + tid;
        int o = i >> 5, j = i & 31;
        out[(bN * 0 + ((size_t)b * O + o) * N) + n0 + j] = obuf[o * 33 + j];
    }
}

extern "C" void kernel_launch(void* const* d_in, const int* in_sizes, int n_in,
                              void* d_out, int out_size) {
    (void)in_sizes; (void)n_in; (void)out_size;
    const float* x  = (const float*)d_in[0];
    const float* W1 = (const float*)d_in[1];
    const float* W2 = (const float*)d_in[2];
    float* out = (float*)d_out;

    prep_kernel<<<(BATCH * N) / 256, 256>>>(x);
    wtrans_kernel<<<(C2 * C2) / 256, 256>>>(W1, W2);
    knn_kernel<<<dim3(N / 64, BATCH), 128>>>();
    mlp_kernel<<<dim3(N / NB, BATCH), 256>>>(out);
}